// round 3
// baseline (speedup 1.0000x reference)
#include <cuda_runtime.h>
#include <math.h>
#include <stdint.h>

#define BB 64
#define TT 512
#define DD 256
#define HSZ 256
#define G4 1024
#define HS2 512
#define PITCH 260

// ---------------- device scratch (static: no allocation) ----------------
__device__ float g_XW[(size_t)TT * BB * G4];  // [t][b][gatecol]  128MB
__device__ float g_preH[BB * HSZ];
__device__ float g_preC[BB * HSZ];
__device__ float g_h[BB * HSZ];
__device__ float g_c[BB * HSZ];
__device__ unsigned g_bar[8];

// output offsets (floats)
#define OFF_HSEQ ((size_t)0)
#define OFF_CSEQ ((size_t)8388608)
#define OFF_HMU  ((size_t)16777216)
#define OFF_HSTD ((size_t)25165824)
#define OFF_CMU  ((size_t)33554432)
#define OFF_CSTD ((size_t)41943040)
#define OFF_HT   ((size_t)50331648)
#define OFF_CT   ((size_t)50348032)

__global__ void bar_reset_kernel() {
    if (threadIdx.x < 8) g_bar[threadIdx.x] = 0u;
}

// ---------------- precompute: XW[t][b][col] = x[b][t][:] @ W_ih + bias ----------------
__global__ __launch_bounds__(256) void xw_kernel(const float* __restrict__ x,
                                                 const float* __restrict__ wih,
                                                 const float* __restrict__ bias) {
    __shared__ float XsT[64 * 68];  // [k][t] padded
    __shared__ float Ws[64 * 64];   // [k][col]
    const int bx = blockIdx.x;      // 0..15  col block (64 cols)
    const int by = blockIdx.y;      // 0..7   t block (64 t)
    const int bz = blockIdx.z;      // 0..63  b
    const int tid = threadIdx.x;
    const int tx = tid & 15;        // col quad
    const int ty = tid >> 4;        // t quad

    float acc[4][4];
#pragma unroll
    for (int i = 0; i < 4; i++)
#pragma unroll
        for (int j = 0; j < 4; j++) acc[i][j] = 0.f;

    for (int kc = 0; kc < 4; kc++) {
        const int k0 = kc * 64;
        __syncthreads();
        for (int i = tid; i < 4096; i += 256) {
            int kk = i >> 6, cc = i & 63;
            Ws[kk * 64 + cc] = wih[(size_t)(k0 + kk) * G4 + bx * 64 + cc];
        }
        for (int i = tid; i < 4096; i += 256) {
            int tt2 = i >> 6, kk = i & 63;
            XsT[kk * 68 + tt2] = x[((size_t)bz * TT + by * 64 + tt2) * DD + k0 + kk];
        }
        __syncthreads();
#pragma unroll 8
        for (int kk = 0; kk < 64; kk++) {
            float4 av = *(const float4*)&XsT[kk * 68 + ty * 4];
            float4 wv = *(const float4*)&Ws[kk * 64 + tx * 4];
            acc[0][0] = fmaf(av.x, wv.x, acc[0][0]);
            acc[0][1] = fmaf(av.x, wv.y, acc[0][1]);
            acc[0][2] = fmaf(av.x, wv.z, acc[0][2]);
            acc[0][3] = fmaf(av.x, wv.w, acc[0][3]);
            acc[1][0] = fmaf(av.y, wv.x, acc[1][0]);
            acc[1][1] = fmaf(av.y, wv.y, acc[1][1]);
            acc[1][2] = fmaf(av.y, wv.z, acc[1][2]);
            acc[1][3] = fmaf(av.y, wv.w, acc[1][3]);
            acc[2][0] = fmaf(av.z, wv.x, acc[2][0]);
            acc[2][1] = fmaf(av.z, wv.y, acc[2][1]);
            acc[2][2] = fmaf(av.z, wv.z, acc[2][2]);
            acc[2][3] = fmaf(av.z, wv.w, acc[2][3]);
            acc[3][0] = fmaf(av.w, wv.x, acc[3][0]);
            acc[3][1] = fmaf(av.w, wv.y, acc[3][1]);
            acc[3][2] = fmaf(av.w, wv.z, acc[3][2]);
            acc[3][3] = fmaf(av.w, wv.w, acc[3][3]);
        }
    }
    const int col0 = bx * 64 + tx * 4;
    const float4 bv = *(const float4*)&bias[col0];
#pragma unroll
    for (int i = 0; i < 4; i++) {
        int t = by * 64 + ty * 4 + i;
        float4 v;
        v.x = acc[i][0] + bv.x;
        v.y = acc[i][1] + bv.y;
        v.z = acc[i][2] + bv.z;
        v.w = acc[i][3] + bv.w;
        *(float4*)&g_XW[((size_t)t * BB + bz) * G4 + col0] = v;
    }
}

// ---------------- persistent recurrent kernel ----------------
__device__ __forceinline__ float sigmoidf_(float v) { return 1.f / (1.f + expf(-v)); }

__device__ __forceinline__ void rg_barrier(int rg, unsigned target) {
    __syncthreads();
    if (threadIdx.x == 0) {
        __threadfence();
        atomicAdd(&g_bar[rg], 1u);
        while (*(volatile unsigned*)&g_bar[rg] < target) { }
        __threadfence();
    }
    __syncthreads();
}

#define SMEM_FLOATS (2 * 64 * PITCH + 3 * 8 * PITCH + 2 * 512)
#define SMEM_BYTES (SMEM_FLOATS * 4)

__global__ __launch_bounds__(256, 1) void lstm_kernel(const float* __restrict__ whh,
                                                      const float* __restrict__ hrep,
                                                      const float* __restrict__ crep,
                                                      const float* __restrict__ eps_h,
                                                      const float* __restrict__ eps_c,
                                                      float* __restrict__ out) {
    extern __shared__ float smem[];
    float* WaT = smem;                    // [64][PITCH]  gate-weight slice (transposed)
    float* WbT = WaT + 64 * PITCH;        // [64][PITCH]  reparam-weight slice (transposed)
    float* Hs  = WbT + 64 * PITCH;        // [8][PITCH]
    float* PH  = Hs + 8 * PITCH;          // [8][PITCH]
    float* PC  = PH + 8 * PITCH;          // [8][PITCH]
    float* Gs  = PC + 8 * PITCH;          // [64][8]
    float* Ps  = Gs + 512;                // [64][8]

    const int tid = threadIdx.x;
    const int rg = blockIdx.x >> 4;       // row group: rows rg*8 .. rg*8+7
    const int cb = blockIdx.x & 15;       // col block: j in [cb*16, cb*16+16)

    // ---- one-time weight load into SMEM ----
    for (int i = tid; i < 64 * 256; i += 256) {
        int c = i & 63, k = i >> 6;
        int gcol = (c >> 4) * 256 + cb * 16 + (c & 15);
        WaT[c * PITCH + k] = whh[(size_t)k * G4 + gcol];
        int mm = c >> 5, hf = (c >> 4) & 1, jj = c & 15;
        int col2 = hf * 256 + cb * 16 + jj;
        WbT[c * PITCH + k] = (mm ? crep : hrep)[(size_t)k * HS2 + col2];
    }
    __syncthreads();

    // GEMM thread mapping
    const int c = tid >> 2;               // 0..63 (column within slice)
    const int rh = tid & 3;               // rows rh, rh+4
    const int gcol = (c >> 4) * 256 + cb * 16 + (c & 15);
    const int mb = c >> 5;                // phase-B matrix select
    // sampling thread mapping
    const int smm = tid >> 7, srow = (tid >> 4) & 7, sjj = tid & 15;
    const int sb = rg * 8 + srow, sj = cb * 16 + sjj;
    const float* epsp = smm ? eps_c : eps_h;
    const size_t off_seq = smm ? OFF_CSEQ : OFF_HSEQ;
    const size_t off_mu  = smm ? OFF_CMU  : OFF_HMU;
    const size_t off_std = smm ? OFF_CSTD : OFF_HSTD;
    const size_t off_fin = smm ? OFF_CT   : OFF_HT;
    float* statep = smm ? g_c : g_h;

    unsigned target = 0;

    for (int t = 0; t < TT; t++) {
        // ---- stage h rows ----
        if (t == 0) {
            for (int i = tid; i < 2048; i += 256) {
                int r = i >> 8, k = i & 255;
                Hs[r * PITCH + k] = 0.f;
            }
        } else {
            for (int i = tid; i < 2048; i += 256) {
                int r = i >> 8, k = i & 255;
                Hs[r * PITCH + k] = __ldcg(&g_h[(rg * 8 + r) * HSZ + k]);
            }
        }
        __syncthreads();

        // ---- phase A: gates tile = XW[t] + h @ W_hh ----
        {
            const int base = (t * BB + rg * 8 + rh) * G4 + gcol;
            float a0 = __ldcg(&g_XW[base]);
            float a1 = __ldcg(&g_XW[base + 4 * G4]);
            const float4* wv = (const float4*)&WaT[c * PITCH];
            const float4* ha = (const float4*)&Hs[rh * PITCH];
            const float4* hb = (const float4*)&Hs[(rh + 4) * PITCH];
            float p0 = 0.f, q0 = 0.f, p1 = 0.f, q1 = 0.f;
#pragma unroll 16
            for (int i = 0; i < 64; i++) {
                float4 w = wv[i];
                float4 u = ha[i];
                float4 v = hb[i];
                p0 = fmaf(u.x, w.x, p0); q0 = fmaf(u.y, w.y, q0);
                p0 = fmaf(u.z, w.z, p0); q0 = fmaf(u.w, w.w, q0);
                p1 = fmaf(v.x, w.x, p1); q1 = fmaf(v.y, w.y, q1);
                p1 = fmaf(v.z, w.z, p1); q1 = fmaf(v.w, w.w, q1);
            }
            Gs[c * 8 + rh] = a0 + p0 + q0;
            Gs[c * 8 + rh + 4] = a1 + p1 + q1;
        }
        __syncthreads();

        // ---- nonlinearity -> pre_c, pre_h ----
        if (tid < 128) {
            int r = tid >> 4, jj = tid & 15;
            float vi = sigmoidf_(Gs[((0 << 4) | jj) * 8 + r]);
            float vf = sigmoidf_(Gs[((1 << 4) | jj) * 8 + r]);
            float vg = tanhf(Gs[((2 << 4) | jj) * 8 + r]);
            float vo = sigmoidf_(Gs[((3 << 4) | jj) * 8 + r]);
            int b = rg * 8 + r, j = cb * 16 + jj;
            float cold = (t == 0) ? 0.f : __ldcg(&g_c[b * HSZ + j]);
            float pc = vf * cold + vi * vg;
            float ph = vo * tanhf(cold);
            __stcg(&g_preC[b * HSZ + j], pc);
            __stcg(&g_preH[b * HSZ + j], ph);
        }
        target += 16;
        rg_barrier(rg, target);

        // ---- stage pre rows ----
        for (int i = tid; i < 2048; i += 256) {
            int r = i >> 8, k = i & 255;
            PH[r * PITCH + k] = __ldcg(&g_preH[(rg * 8 + r) * HSZ + k]);
            PC[r * PITCH + k] = __ldcg(&g_preC[(rg * 8 + r) * HSZ + k]);
        }
        // prefetch eps for sampling (hide DRAM latency behind GEMM B)
        float ep = __ldg(&epsp[((size_t)t * BB + sb) * HSZ + sj]);
        __syncthreads();

        // ---- phase B: reparam GEMM ----
        {
            const float* src = mb ? PC : PH;
            const float4* wv = (const float4*)&WbT[c * PITCH];
            const float4* ha = (const float4*)&src[rh * PITCH];
            const float4* hb = (const float4*)&src[(rh + 4) * PITCH];
            float p0 = 0.f, q0 = 0.f, p1 = 0.f, q1 = 0.f;
#pragma unroll 16
            for (int i = 0; i < 64; i++) {
                float4 w = wv[i];
                float4 u = ha[i];
                float4 v = hb[i];
                p0 = fmaf(u.x, w.x, p0); q0 = fmaf(u.y, w.y, q0);
                p0 = fmaf(u.z, w.z, p0); q0 = fmaf(u.w, w.w, q0);
                p1 = fmaf(v.x, w.x, p1); q1 = fmaf(v.y, w.y, q1);
                p1 = fmaf(v.z, w.z, p1); q1 = fmaf(v.w, w.w, q1);
            }
            Ps[c * 8 + rh] = p0 + q0;
            Ps[c * 8 + rh + 4] = p1 + q1;
        }
        __syncthreads();

        // ---- sample + write outputs + update state ----
        {
            float mu = Ps[((smm << 5) | sjj) * 8 + srow];
            float sr = Ps[((smm << 5) | 16 | sjj) * 8 + srow];
            mu = fminf(fmaxf(mu, 1e-6f), 1e6f);
            float sp = fmaxf(sr, 0.f) + log1pf(expf(-fabsf(sr)));
            float sd = fmaxf(sp, 1e-6f);
            float val = fmaf(ep, sd, mu);
            __stcg(&statep[sb * HSZ + sj], val);
            size_t o = (size_t)sb * (TT * HSZ) + (size_t)t * HSZ + sj;
            out[off_seq + o] = val;
            out[off_mu + o] = mu;
            out[off_std + o] = sd;
            if (t == TT - 1) out[off_fin + sb * HSZ + sj] = val;
        }
        target += 16;
        rg_barrier(rg, target);
    }
}

// ---------------- launch ----------------
extern "C" void kernel_launch(void* const* d_in, const int* in_sizes, int n_in,
                              void* d_out, int out_size) {
    (void)in_sizes; (void)n_in; (void)out_size;
    const float* x     = (const float*)d_in[0];
    const float* wih   = (const float*)d_in[1];
    const float* whh   = (const float*)d_in[2];
    const float* bias  = (const float*)d_in[3];
    const float* hrep  = (const float*)d_in[4];
    const float* crep  = (const float*)d_in[5];
    const float* eps_h = (const float*)d_in[6];
    const float* eps_c = (const float*)d_in[7];
    float* out = (float*)d_out;

    cudaFuncSetAttribute(lstm_kernel, cudaFuncAttributeMaxDynamicSharedMemorySize, SMEM_BYTES);

    bar_reset_kernel<<<1, 32>>>();
    xw_kernel<<<dim3(16, 8, 64), 256>>>(x, wih, bias);
    lstm_kernel<<<128, 256, SMEM_BYTES>>>(whh, hrep, crep, eps_h, eps_c, out);
}